// round 8
// baseline (speedup 1.0000x reference)
#include <cuda_runtime.h>
#include <cuda_bf16.h>
#include <stdint.h>

// Problem constants (fixed by the reference: T=8, L=2,000,000, B=16,384)
#define T_TABLES 8
#define L_PER_TABLE 2000000
#define B_BATCH 16384           // power of two -> shift/mask indexing
#define B_LOG2 14
#define TL (T_TABLES * L_PER_TABLE)          // 16,000,000
#define N4 (TL / 4)                          // 4,000,000 float4 per big region
#define OFF_OUT (T_TABLES * B_BATCH + 1)     // 131,073
#define OFF_IN_STRIDE (B_BATCH + 1)          // 16,385

// out layout (float32):
//   [0, TL)                        : float(combined_indices)        (16B aligned)
//   [TL, TL+OFF_OUT)               : float(combined_offsets)
//   [TL+OFF_OUT, TL+OFF_OUT+TL)    : combined_weights (starts at index ==1 mod 4)
//
// Weights stores shifted down by 1 float for 16B alignment:
//   store m writes out[W_ALIGN_BASE+4m .. +3] = { w[4m-1], w[4m], w[4m+1], w[4m+2] }
// Slot at W_ALIGN_BASE is combined_offsets' LAST element == (float)TL (constant).
// Tail w[TL-1] written by the last weights thread (it's b3.w, already in regs).
#define W_OUT_START   (TL + OFF_OUT)         // 16,131,073
#define W_ALIGN_BASE  (W_OUT_START - 1)      // 16,131,072 (16B aligned)

#define THREADS 256
#define UNROLL 4
#define IDX_THREADS (N4 / UNROLL)            // 1,000,000
#define WT_THREADS  (N4 / UNROLL)            // 1,000,000
#define OFF_BODY    (OFF_OUT - 1)            // 131,072
#define IDX_BLOCKS  ((IDX_THREADS + THREADS - 1) / THREADS)  // 3907 (1M/256 = 3906.25 -> pad)
#define WT_BLOCKS   IDX_BLOCKS
#define OFF_BLOCKS  (OFF_BODY / THREADS)                      // 512 (exact)
#define TOTAL_BLOCKS (IDX_BLOCKS + WT_BLOCKS + OFF_BLOCKS)

__global__ void __launch_bounds__(THREADS)
tbe_fused_kernel(const int4* __restrict__ idx4,
                 const int* __restrict__ offs,
                 const float4* __restrict__ w4,
                 const float* __restrict__ w,
                 float* __restrict__ out) {
    int bid = blockIdx.x;

    if (bid < IDX_BLOCKS) {
        // ---- indices -> float: 4 independent int4 loads (MLP=4) ----
        int t = bid * THREADS + threadIdx.x;
        if (t < IDX_THREADS) {
            int base = t * UNROLL;
            int4 v0 = idx4[base + 0];
            int4 v1 = idx4[base + 1];
            int4 v2 = idx4[base + 2];
            int4 v3 = idx4[base + 3];
            float4* o = (float4*)out;
            o[base + 0] = make_float4((float)v0.x, (float)v0.y, (float)v0.z, (float)v0.w);
            o[base + 1] = make_float4((float)v1.x, (float)v1.y, (float)v1.z, (float)v1.w);
            o[base + 2] = make_float4((float)v2.x, (float)v2.y, (float)v2.z, (float)v2.w);
            o[base + 3] = make_float4((float)v3.x, (float)v3.y, (float)v3.z, (float)v3.w);
        }
    } else if (bid < IDX_BLOCKS + WT_BLOCKS) {
        // ---- weights copy, store-shifted by one float: 4 independent loads ----
        int t = (bid - IDX_BLOCKS) * THREADS + threadIdx.x;
        if (t < WT_THREADS) {
            int base = t * UNROLL;                   // float4 index
            float4 b0 = w4[base + 0];
            float4 b1 = w4[base + 1];
            float4 b2 = w4[base + 2];
            float4 b3 = w4[base + 3];
            // w[16t-1] = lane-1's b3.w; lane 0 loads it (or writes constant TL at t=0)
            float prev0 = __shfl_up_sync(0xFFFFFFFFu, b3.w, 1);
            if ((threadIdx.x & 31) == 0) {
                prev0 = (t > 0) ? w[4 * base - 1] : (float)TL;
            }
            float4* wout = (float4*)(out + W_ALIGN_BASE);
            wout[base + 0] = make_float4(prev0, b0.x, b0.y, b0.z);
            wout[base + 1] = make_float4(b0.w,  b1.x, b1.y, b1.z);
            wout[base + 2] = make_float4(b1.w,  b2.x, b2.y, b2.z);
            wout[base + 3] = make_float4(b2.w,  b3.x, b3.y, b3.z);
            if (t == WT_THREADS - 1) {
                out[W_OUT_START + (TL - 1)] = b3.w;  // tail element
            }
        }
    } else {
        // ---- combined_offsets body (last element handled by weights t=0) ----
        int j = (bid - IDX_BLOCKS - WT_BLOCKS) * THREADS + threadIdx.x;
        if (j < OFF_BODY) {
            int tt = j >> B_LOG2;
            int r = j & (B_BATCH - 1);
            out[TL + j] = (float)(offs[tt * OFF_IN_STRIDE + r] + tt * L_PER_TABLE);
        }
    }
}

extern "C" void kernel_launch(void* const* d_in, const int* in_sizes, int n_in,
                              void* d_out, int out_size) {
    const int* indices = (const int*)d_in[0];       // [T, L] int32
    const int* offsets = (const int*)d_in[1];       // [T, B+1] int32
    const float* weights = (const float*)d_in[2];   // [T, L] float32
    float* out = (float*)d_out;

    tbe_fused_kernel<<<TOTAL_BLOCKS, THREADS>>>(
        (const int4*)indices, offsets, (const float4*)weights, weights, out);
}

// round 9
// speedup vs baseline: 1.0951x; 1.0951x over previous
#include <cuda_runtime.h>
#include <cuda_bf16.h>
#include <stdint.h>

// Problem constants (fixed by the reference: T=8, L=2,000,000, B=16,384)
#define T_TABLES 8
#define L_PER_TABLE 2000000
#define B_BATCH 16384           // power of two -> shift/mask indexing
#define B_LOG2 14
#define TL (T_TABLES * L_PER_TABLE)          // 16,000,000
#define N4 (TL / 4)                          // 4,000,000 float4 per big region
#define OFF_OUT (T_TABLES * B_BATCH + 1)     // 131,073
#define OFF_IN_STRIDE (B_BATCH + 1)          // 16,385

// out layout (float32):
//   [0, TL)                        : float(combined_indices)        (16B aligned)
//   [TL, TL+OFF_OUT)               : float(combined_offsets)
//   [TL+OFF_OUT, TL+OFF_OUT+TL)    : combined_weights (starts at index ==1 mod 4)
//
// Weights stores shifted down by 1 float for 16B alignment:
//   store m writes out[W_ALIGN_BASE+4m .. +3] = { w[4m-1], w[4m], w[4m+1], w[4m+2] }
// Slot at W_ALIGN_BASE is combined_offsets' LAST element == (float)TL (constant).
// Tail w[TL-1] is written by the m == N4-1 store thread (it's b.w, in regs).
#define W_OUT_START   (TL + OFF_OUT)         // 16,131,073
#define W_ALIGN_BASE  (W_OUT_START - 1)      // 16,131,072 (16B aligned)

#define THREADS 256
#define UNROLL 4
#define F4_PER_BLOCK (THREADS * UNROLL)                       // 1024
#define IDX_BLOCKS  ((N4 + F4_PER_BLOCK - 1) / F4_PER_BLOCK) // 3907
#define WT_BLOCKS   IDX_BLOCKS
#define OFF_BODY    (OFF_OUT - 1)                             // 131,072
#define OFF_BLOCKS  (OFF_BODY / THREADS)                      // 512 (exact)
#define TOTAL_BLOCKS (IDX_BLOCKS + WT_BLOCKS + OFF_BLOCKS)

__global__ void __launch_bounds__(THREADS)
tbe_fused_kernel(const int4* __restrict__ idx4,
                 const int* __restrict__ offs,
                 const float4* __restrict__ w4,
                 const float* __restrict__ w,
                 float* __restrict__ out) {
    int bid = blockIdx.x;

    if (bid < IDX_BLOCKS) {
        // ---- indices -> float: block-strided 4x unroll, each LDG coalesced ----
        int base = bid * F4_PER_BLOCK + threadIdx.x;
        int4 v[UNROLL];
        bool ok[UNROLL];
        #pragma unroll
        for (int u = 0; u < UNROLL; u++) {
            int m = base + u * THREADS;
            ok[u] = (m < N4);
            if (ok[u]) v[u] = idx4[m];
        }
        float4* o = (float4*)out;
        #pragma unroll
        for (int u = 0; u < UNROLL; u++) {
            int m = base + u * THREADS;
            if (ok[u])
                o[m] = make_float4((float)v[u].x, (float)v[u].y,
                                   (float)v[u].z, (float)v[u].w);
        }
    } else if (bid < IDX_BLOCKS + WT_BLOCKS) {
        // ---- weights copy, store-shifted by one float ----
        int base = (bid - IDX_BLOCKS) * F4_PER_BLOCK + threadIdx.x;
        float4 b[UNROLL];
        bool ok[UNROLL];
        #pragma unroll
        for (int u = 0; u < UNROLL; u++) {
            int m = base + u * THREADS;
            ok[u] = (m < N4);
            if (ok[u]) b[u] = w4[m];
        }
        int lane = threadIdx.x & 31;
        float4* wout = (float4*)(out + W_ALIGN_BASE);
        #pragma unroll
        for (int u = 0; u < UNROLL; u++) {
            int m = base + u * THREADS;
            // prev = w[4m-1] = lane-1's b[u].w (same instruction group)
            float prev = __shfl_up_sync(0xFFFFFFFFu, b[u].w, 1);
            if (ok[u]) {
                if (lane == 0)
                    prev = (m > 0) ? w[4 * m - 1] : (float)TL;
                wout[m] = make_float4(prev, b[u].x, b[u].y, b[u].z);
                if (m == N4 - 1)
                    out[W_OUT_START + (TL - 1)] = b[u].w;  // tail element
            }
        }
    } else {
        // ---- combined_offsets body (last element handled by weights m=0) ----
        int j = (bid - IDX_BLOCKS - WT_BLOCKS) * THREADS + threadIdx.x;
        if (j < OFF_BODY) {
            int tt = j >> B_LOG2;
            int r = j & (B_BATCH - 1);
            out[TL + j] = (float)(offs[tt * OFF_IN_STRIDE + r] + tt * L_PER_TABLE);
        }
    }
}

extern "C" void kernel_launch(void* const* d_in, const int* in_sizes, int n_in,
                              void* d_out, int out_size) {
    const int* indices = (const int*)d_in[0];       // [T, L] int32
    const int* offsets = (const int*)d_in[1];       // [T, B+1] int32
    const float* weights = (const float*)d_in[2];   // [T, L] float32
    float* out = (float*)d_out;

    tbe_fused_kernel<<<TOTAL_BLOCKS, THREADS>>>(
        (const int4*)indices, offsets, (const float4*)weights, weights, out);
}

// round 10
// speedup vs baseline: 1.1312x; 1.0330x over previous
#include <cuda_runtime.h>
#include <cuda_bf16.h>
#include <stdint.h>

// Problem constants (fixed by the reference: T=8, L=2,000,000, B=16,384)
#define T_TABLES 8
#define L_PER_TABLE 2000000
#define B_BATCH 16384           // power of two -> shift/mask indexing
#define B_LOG2 14
#define TL (T_TABLES * L_PER_TABLE)          // 16,000,000
#define N4 (TL / 4)                          // 4,000,000 float4 per big region
#define OFF_OUT (T_TABLES * B_BATCH + 1)     // 131,073
#define OFF_IN_STRIDE (B_BATCH + 1)          // 16,385

// out layout (float32):
//   [0, TL)                        : float(combined_indices)        (16B aligned)
//   [TL, TL+OFF_OUT)               : float(combined_offsets)
//   [TL+OFF_OUT, TL+OFF_OUT+TL)    : combined_weights (starts at index ==1 mod 4)
//
// Weights stores shifted down by 1 float for 16B alignment:
//   store m writes out[W_ALIGN_BASE+4m .. +3] = { w[4m-1], w[4m], w[4m+1], w[4m+2] }
// Slot at W_ALIGN_BASE is combined_offsets' LAST element == (float)TL (constant).
// Tail w[TL-1] is written by the m == N4-1 store thread (it's b.w, in regs).
#define W_OUT_START   (TL + OFF_OUT)         // 16,131,073
#define W_ALIGN_BASE  (W_OUT_START - 1)      // 16,131,072 (16B aligned)

#define THREADS 256
#define UNROLL 5                              // 256*5 = 1280; N4/1280 = 3125 EXACT
#define F4_PER_BLOCK (THREADS * UNROLL)       // 1280
#define IDX_BLOCKS  (N4 / F4_PER_BLOCK)       // 3125 (exact, no predicates)
#define WT_BLOCKS   IDX_BLOCKS
#define OFF_BODY    (OFF_OUT - 1)             // 131,072
#define OFF_BLOCKS  (OFF_BODY / THREADS)      // 512 (exact)
#define TOTAL_BLOCKS (IDX_BLOCKS + WT_BLOCKS + OFF_BLOCKS)

__global__ void __launch_bounds__(THREADS)
tbe_fused_kernel(const int4* __restrict__ idx4,
                 const int* __restrict__ offs,
                 const float4* __restrict__ w4,
                 const float* __restrict__ w,
                 float* __restrict__ out) {
    int bid = blockIdx.x;

    if (bid < IDX_BLOCKS) {
        // ---- indices -> float: block-strided 5x unroll, every LDG/STG coalesced ----
        int base = bid * F4_PER_BLOCK + threadIdx.x;
        int4 v[UNROLL];
        #pragma unroll
        for (int u = 0; u < UNROLL; u++)
            v[u] = __ldcs(&idx4[base + u * THREADS]);     // evict-first stream
        float4* o = (float4*)out;
        #pragma unroll
        for (int u = 0; u < UNROLL; u++)
            __stcs(&o[base + u * THREADS],
                   make_float4((float)v[u].x, (float)v[u].y,
                               (float)v[u].z, (float)v[u].w));
    } else if (bid < IDX_BLOCKS + WT_BLOCKS) {
        // ---- weights copy, store-shifted by one float ----
        int base = (bid - IDX_BLOCKS) * F4_PER_BLOCK + threadIdx.x;
        float4 b[UNROLL];
        #pragma unroll
        for (int u = 0; u < UNROLL; u++)
            b[u] = __ldcs(&w4[base + u * THREADS]);
        int lane = threadIdx.x & 31;
        float4* wout = (float4*)(out + W_ALIGN_BASE);
        #pragma unroll
        for (int u = 0; u < UNROLL; u++) {
            int m = base + u * THREADS;
            // prev = w[4m-1] = lane-1's b[u].w (same load instruction group)
            float prev = __shfl_up_sync(0xFFFFFFFFu, b[u].w, 1);
            if (lane == 0)
                prev = (m > 0) ? w[4 * m - 1] : (float)TL;  // m==0: offsets' last slot
            __stcs(&wout[m], make_float4(prev, b[u].x, b[u].y, b[u].z));
            if (m == N4 - 1)
                out[W_OUT_START + (TL - 1)] = b[u].w;        // tail element
        }
    } else {
        // ---- combined_offsets body (last element handled by weights m=0) ----
        int j = (bid - IDX_BLOCKS - WT_BLOCKS) * THREADS + threadIdx.x;
        int tt = j >> B_LOG2;
        int r = j & (B_BATCH - 1);
        out[TL + j] = (float)(offs[tt * OFF_IN_STRIDE + r] + tt * L_PER_TABLE);
    }
}

extern "C" void kernel_launch(void* const* d_in, const int* in_sizes, int n_in,
                              void* d_out, int out_size) {
    const int* indices = (const int*)d_in[0];       // [T, L] int32
    const int* offsets = (const int*)d_in[1];       // [T, B+1] int32
    const float* weights = (const float*)d_in[2];   // [T, L] float32
    float* out = (float*)d_out;

    tbe_fused_kernel<<<TOTAL_BLOCKS, THREADS>>>(
        (const int4*)indices, offsets, (const float4*)weights, weights, out);
}